// round 2
// baseline (speedup 1.0000x reference)
#include <cuda_runtime.h>

#define BB 2
#define NN 131072
#define KK 20
#define EE 256
#define TEMP_INV 20.0f
#define SCORE_THRESH 0.04f

typedef unsigned long long u64;

// ---- packed f32x2 helpers (FFMA2 is PTX-only on sm_103a) ----
__device__ __forceinline__ u64 fma2(u64 a, u64 b, u64 c) {
    u64 d; asm("fma.rn.f32x2 %0, %1, %2, %3;" : "=l"(d) : "l"(a), "l"(b), "l"(c));
    return d;
}
__device__ __forceinline__ u64 pk(float a, float b) {
    u64 r; asm("mov.b64 %0, {%1, %2};" : "=l"(r) : "f"(a), "f"(b)); return r;
}
__device__ __forceinline__ float f2sum(u64 v) {
    float lo, hi; asm("mov.b64 {%0, %1}, %2;" : "=f"(lo), "=f"(hi) : "l"(v));
    return lo + hi;
}

// ---- scratch (device globals: no allocations allowed) ----
__device__ float g_x[BB * KK * EE];        // x after GEMM1 (layout [b][k][o])
__device__ float g_sn[BB * KK * EE];       // normalized slots * (1/TEMP), [b][k][e]
__device__ float g_scores[BB * KK];        // per-k softmax sums
__device__ int   g_outsrc[BB * KK];        // output slot p -> source k (-1 = zero)
__device__ float g_mask[(size_t)BB * KK * NN]; // softmax masks, [b][k][n] (21 MB)

// ============================================================
// k1a: x[b][k][o] = sum_e slots[b][k][e] * w1[o][e] + b1[o]
// one thread per (b,k,o); also zeroes score accumulators.
// ============================================================
__global__ void k1a(const float* __restrict__ slots, const float* __restrict__ w1,
                    const float* __restrict__ b1) {
    int g = blockIdx.x * 256 + threadIdx.x;       // 0 .. B*K*E-1 (grid exact)
    if (g < BB * KK) g_scores[g] = 0.f;
    int b = g / (KK * EE);
    int rem = g % (KK * EE);
    int k = rem / EE;
    int o = rem % EE;
    const float4* sr = (const float4*)(slots + (size_t)(b * KK + k) * EE);
    const float4* wr = (const float4*)(w1 + (size_t)o * EE);
    u64 acc = 0;
#pragma unroll 8
    for (int i = 0; i < EE / 4; i++) {
        float4 s = __ldg(&sr[i]);
        float4 w = __ldg(&wr[i]);
        acc = fma2(pk(w.x, w.y), pk(s.x, s.y), acc);
        acc = fma2(pk(w.z, w.w), pk(s.z, s.w), acc);
    }
    g_x[(b * KK + k) * EE + o] = f2sum(acc) + __ldg(&b1[o]);
}

// ============================================================
// k1b: GroupNorm over (64 channels x 20 slots) per (b, group) + affine + ReLU
// grid = B*4 blocks, 256 threads
// ============================================================
__global__ void k1b(const float* __restrict__ gn_g, const float* __restrict__ gn_b) {
    int b = blockIdx.x >> 2, grp = blockIdx.x & 3;
    int t = threadIdx.x;
    float s = 0.f, ss = 0.f;
    for (int i = t; i < KK * 64; i += 256) {
        int k = i >> 6, oo = (i & 63) + grp * 64;
        float v = g_x[(b * KK + k) * EE + oo];
        s += v; ss += v * v;
    }
    __shared__ float rs[8], rss[8];
    for (int off = 16; off; off >>= 1) {
        s  += __shfl_xor_sync(0xffffffffu, s, off);
        ss += __shfl_xor_sync(0xffffffffu, ss, off);
    }
    if ((t & 31) == 0) { rs[t >> 5] = s; rss[t >> 5] = ss; }
    __syncthreads();
    if (t == 0) {
        float a = 0.f, q = 0.f;
        for (int i = 0; i < 8; i++) { a += rs[i]; q += rss[i]; }
        rs[0] = a; rss[0] = q;
    }
    __syncthreads();
    float mu  = rs[0] * (1.f / 1280.f);
    float var = rss[0] * (1.f / 1280.f) - mu * mu;
    float sc  = rsqrtf(var + 1e-5f);
    for (int i = t; i < KK * 64; i += 256) {
        int k = i >> 6, oo = (i & 63) + grp * 64;
        int idx = (b * KK + k) * EE + oo;
        float v = (g_x[idx] - mu) * sc * __ldg(&gn_g[oo]) + __ldg(&gn_b[oo]);
        g_x[idx] = fmaxf(v, 0.f);
    }
}

// ============================================================
// k1c: slot[b][f][k] = sum_o x[b][o][k] * w2[f][o] + b2[f], then l2norm over f,
//      scale by 1/TEMP. One block per (b,k), thread = f.
// ============================================================
__global__ void k1c(const float* __restrict__ w2, const float* __restrict__ b2) {
    int b = blockIdx.x / KK, k = blockIdx.x % KK;
    int f = threadIdx.x;
    __shared__ float sx[EE];
    sx[f] = g_x[(b * KK + k) * EE + f];
    __syncthreads();
    const float4* wr = (const float4*)(w2 + (size_t)f * EE);
    const float4* xr = (const float4*)sx;
    u64 acc = 0;
#pragma unroll 8
    for (int i = 0; i < EE / 4; i++) {
        float4 w = __ldg(&wr[i]);
        float4 x = xr[i];
        acc = fma2(pk(w.x, w.y), pk(x.x, x.y), acc);
        acc = fma2(pk(w.z, w.w), pk(x.z, x.w), acc);
    }
    float d = f2sum(acc) + __ldg(&b2[f]);
    float q = d * d;
    __shared__ float rq[8];
    for (int off = 16; off; off >>= 1) q += __shfl_xor_sync(0xffffffffu, q, off);
    if ((f & 31) == 0) rq[f >> 5] = q;
    __syncthreads();
    __shared__ float rinv_s;
    if (f == 0) {
        float a = 0.f;
        for (int i = 0; i < 8; i++) a += rq[i];
        rinv_s = rsqrtf(fmaxf(a, 1e-24f)) * TEMP_INV;
    }
    __syncthreads();
    g_sn[(b * KK + k) * EE + f] = d * rinv_s;
}

// ============================================================
// k2: the big one. thread = one feature row (b,n):
//   raw dots with 20 sn columns + ||f||^2, all via packed FFMA2,
//   softmax over 20, write mask[b][k][n] (coalesced), accumulate score sums.
// ============================================================
__global__ void __launch_bounds__(256) k2(const float* __restrict__ features) {
    __shared__ ulonglong2 s_sn[KK * 64];  // 20 KB: sn[k][e-quad]
    __shared__ float s_sc[KK];
    int t = threadIdx.x;
    const int bpb = NN / 256;
    int b = blockIdx.x / bpb;
    int n = (blockIdx.x % bpb) * 256 + t;

    const ulonglong2* gs = (const ulonglong2*)(g_sn + (size_t)b * KK * EE);
    for (int i = t; i < KK * 64; i += 256) s_sn[i] = gs[i];
    if (t < KK) s_sc[t] = 0.f;
    __syncthreads();

    const ulonglong2* fv =
        (const ulonglong2*)(features + ((size_t)b * NN + n) * EE);

    u64 acc[KK];
#pragma unroll
    for (int k = 0; k < KK; k++) acc[k] = 0;
    u64 nacc = 0;

#pragma unroll 2
    for (int e4 = 0; e4 < 64; e4++) {
        ulonglong2 f = __ldg(&fv[e4]);
        nacc = fma2(f.x, f.x, nacc);
        nacc = fma2(f.y, f.y, nacc);
#pragma unroll
        for (int k = 0; k < KK; k++) {
            ulonglong2 s = s_sn[k * 64 + e4];   // uniform address -> broadcast
            acc[k] = fma2(f.x, s.x, acc[k]);
            acc[k] = fma2(f.y, s.y, acc[k]);
        }
    }

    float rinv = rsqrtf(fmaxf(f2sum(nacc), 1e-24f));
    float l[KK], m = -1e30f;
#pragma unroll
    for (int k = 0; k < KK; k++) { l[k] = f2sum(acc[k]) * rinv; m = fmaxf(m, l[k]); }
    float s = 0.f;
#pragma unroll
    for (int k = 0; k < KK; k++) { l[k] = __expf(l[k] - m); s += l[k]; }
    float is = 1.f / s;

#pragma unroll
    for (int k = 0; k < KK; k++) {
        float p = l[k] * is;
        g_mask[((size_t)(b * KK + k)) * NN + n] = p;
        float ws = p;
        for (int off = 16; off; off >>= 1) ws += __shfl_xor_sync(0xffffffffu, ws, off);
        if ((t & 31) == 0) atomicAdd(&s_sc[k], ws);
    }
    __syncthreads();
    if (t < KK) atomicAdd(&g_scores[b * KK + t], s_sc[t]);
}

// ============================================================
// k3: NMS logic. Softmax rows sum to 1 => at most one value > 0.5 per row
// => inter is diagonal => IoU off-diagonal = 0 => suppression never fires.
// kept = valid columns in stable descending-score order, compacted.
// ============================================================
__global__ void k3() {
    if (threadIdx.x != 0) return;
    for (int b = 0; b < BB; b++) {
        float sc[KK]; bool used[KK];
        for (int k = 0; k < KK; k++) {
            sc[k] = g_scores[b * KK + k] * (1.f / (float)NN);
            used[k] = false;
        }
        int pos = 0;
        for (int r = 0; r < KK; r++) {
            int best = 0; float bs = -1e30f;
            for (int k = 0; k < KK; k++)
                if (!used[k] && sc[k] > bs) { bs = sc[k]; best = k; }  // stable ties
            used[best] = true;
            if (bs >= SCORE_THRESH) g_outsrc[b * KK + pos++] = best;
        }
        for (; pos < KK; pos++) g_outsrc[b * KK + pos] = -1;
    }
}

// ============================================================
// k4: out[b][p][n] = mask[b][src[p]][n] / (sum_over_kept + 1e-8), 0 if no src.
// Output layout (B,K,N) is exactly reference's transpose(0,2,1). Coalesced.
// ============================================================
__global__ void __launch_bounds__(256) k4(float* __restrict__ out) {
    __shared__ int src[KK];
    int t = threadIdx.x;
    const int bpb = NN / 256;
    int b = blockIdx.x / bpb;
    int n = (blockIdx.x % bpb) * 256 + t;
    if (t < KK) src[t] = g_outsrc[b * KK + t];
    __syncthreads();
    float v[KK]; float s = 0.f;
#pragma unroll
    for (int p = 0; p < KK; p++) {
        int sk = src[p];
        v[p] = (sk >= 0) ? g_mask[((size_t)(b * KK + sk)) * NN + n] : 0.f;
        s += v[p];
    }
    float is = 1.f / (s + 1e-8f);
#pragma unroll
    for (int p = 0; p < KK; p++)
        out[((size_t)(b * KK + p)) * NN + n] = v[p] * is;
}

// ============================================================
extern "C" void kernel_launch(void* const* d_in, const int* in_sizes, int n_in,
                              void* d_out, int out_size) {
    const float* features = (const float*)d_in[0];
    const float* slots    = (const float*)d_in[1];
    const float* w1       = (const float*)d_in[2];
    const float* b1       = (const float*)d_in[3];
    const float* gn_g     = (const float*)d_in[4];
    const float* gn_b     = (const float*)d_in[5];
    const float* w2       = (const float*)d_in[6];
    const float* b2       = (const float*)d_in[7];

    k1a<<<(BB * KK * EE) / 256, 256>>>(slots, w1, b1);
    k1b<<<BB * 4, 256>>>(gn_g, gn_b);
    k1c<<<BB * KK, 256>>>(w2, b2);
    k2<<<(BB * NN) / 256, 256>>>(features);
    k3<<<1, 32>>>();
    k4<<<(BB * NN) / 256, 256>>>((float*)d_out);
}

// round 3
// speedup vs baseline: 1.1276x; 1.1276x over previous
#include <cuda_runtime.h>

#define BB 2
#define NN 131072
#define KK 20
#define EE 256
#define TEMP_INV 20.0f
#define SCORE_THRESH 0.04f

typedef unsigned long long u64;

// ---- packed f32x2 helpers (FFMA2 is PTX-only on sm_103a) ----
__device__ __forceinline__ u64 fma2(u64 a, u64 b, u64 c) {
    u64 d; asm("fma.rn.f32x2 %0, %1, %2, %3;" : "=l"(d) : "l"(a), "l"(b), "l"(c));
    return d;
}
__device__ __forceinline__ u64 pk(float a, float b) {
    u64 r; asm("mov.b64 %0, {%1, %2};" : "=l"(r) : "f"(a), "f"(b)); return r;
}
__device__ __forceinline__ float f2sum(u64 v) {
    float lo, hi; asm("mov.b64 {%0, %1}, %2;" : "=f"(lo), "=f"(hi) : "l"(v));
    return lo + hi;
}
__device__ __forceinline__ void unpk(u64 v, float& lo, float& hi) {
    asm("mov.b64 {%0, %1}, %2;" : "=f"(lo), "=f"(hi) : "l"(v));
}

// ---- scratch (device globals: no allocations allowed) ----
__device__ float g_x[BB * KK * EE];
__device__ float g_sn[BB * KK * EE];       // normalized slots * (1/TEMP), [b][k][e]
__device__ float g_scores[BB * KK];
__device__ int   g_outsrc[BB * KK];
__device__ float g_mask[(size_t)BB * KK * NN]; // [b][k][n]

// ============================================================
// k1a: x[b][k][o] = sum_e slots[b][k][e] * w1[o][e] + b1[o]
// ============================================================
__global__ void k1a(const float* __restrict__ slots, const float* __restrict__ w1,
                    const float* __restrict__ b1) {
    int g = blockIdx.x * 256 + threadIdx.x;
    if (g < BB * KK) g_scores[g] = 0.f;
    int b = g / (KK * EE);
    int rem = g % (KK * EE);
    int k = rem / EE;
    int o = rem % EE;
    const float4* sr = (const float4*)(slots + (size_t)(b * KK + k) * EE);
    const float4* wr = (const float4*)(w1 + (size_t)o * EE);
    u64 acc = 0;
#pragma unroll 8
    for (int i = 0; i < EE / 4; i++) {
        float4 s = __ldg(&sr[i]);
        float4 w = __ldg(&wr[i]);
        acc = fma2(pk(w.x, w.y), pk(s.x, s.y), acc);
        acc = fma2(pk(w.z, w.w), pk(s.z, s.w), acc);
    }
    g_x[(b * KK + k) * EE + o] = f2sum(acc) + __ldg(&b1[o]);
}

// ============================================================
// k1b: GroupNorm (64 ch x 20 slots) per (b, group) + affine + ReLU
// ============================================================
__global__ void k1b(const float* __restrict__ gn_g, const float* __restrict__ gn_b) {
    int b = blockIdx.x >> 2, grp = blockIdx.x & 3;
    int t = threadIdx.x;
    float s = 0.f, ss = 0.f;
    for (int i = t; i < KK * 64; i += 256) {
        int k = i >> 6, oo = (i & 63) + grp * 64;
        float v = g_x[(b * KK + k) * EE + oo];
        s += v; ss += v * v;
    }
    __shared__ float rs[8], rss[8];
    for (int off = 16; off; off >>= 1) {
        s  += __shfl_xor_sync(0xffffffffu, s, off);
        ss += __shfl_xor_sync(0xffffffffu, ss, off);
    }
    if ((t & 31) == 0) { rs[t >> 5] = s; rss[t >> 5] = ss; }
    __syncthreads();
    if (t == 0) {
        float a = 0.f, q = 0.f;
        for (int i = 0; i < 8; i++) { a += rs[i]; q += rss[i]; }
        rs[0] = a; rss[0] = q;
    }
    __syncthreads();
    float mu  = rs[0] * (1.f / 1280.f);
    float var = rss[0] * (1.f / 1280.f) - mu * mu;
    float sc  = rsqrtf(var + 1e-5f);
    for (int i = t; i < KK * 64; i += 256) {
        int k = i >> 6, oo = (i & 63) + grp * 64;
        int idx = (b * KK + k) * EE + oo;
        float v = (g_x[idx] - mu) * sc * __ldg(&gn_g[oo]) + __ldg(&gn_b[oo]);
        g_x[idx] = fmaxf(v, 0.f);
    }
}

// ============================================================
// k1c: slot + l2norm over f, scaled by 1/TEMP. Block per (b,k), thread=f.
// ============================================================
__global__ void k1c(const float* __restrict__ w2, const float* __restrict__ b2) {
    int b = blockIdx.x / KK, k = blockIdx.x % KK;
    int f = threadIdx.x;
    __shared__ float sx[EE];
    sx[f] = g_x[(b * KK + k) * EE + f];
    __syncthreads();
    const float4* wr = (const float4*)(w2 + (size_t)f * EE);
    const float4* xr = (const float4*)sx;
    u64 acc = 0;
#pragma unroll 8
    for (int i = 0; i < EE / 4; i++) {
        float4 w = __ldg(&wr[i]);
        float4 x = xr[i];
        acc = fma2(pk(w.x, w.y), pk(x.x, x.y), acc);
        acc = fma2(pk(w.z, w.w), pk(x.z, x.w), acc);
    }
    float d = f2sum(acc) + __ldg(&b2[f]);
    float q = d * d;
    __shared__ float rq[8];
    for (int off = 16; off; off >>= 1) q += __shfl_xor_sync(0xffffffffu, q, off);
    if ((f & 31) == 0) rq[f >> 5] = q;
    __syncthreads();
    __shared__ float rinv_s;
    if (f == 0) {
        float a = 0.f;
        for (int i = 0; i < 8; i++) a += rq[i];
        rinv_s = rsqrtf(fmaxf(a, 1e-24f)) * TEMP_INV;
    }
    __syncthreads();
    g_sn[(b * KK + k) * EE + f] = d * rinv_s;
}

// ============================================================
// k2: big GEMV-batch + softmax. R=2 rows/thread, k-pair packed accumulators.
//   smem sn layout: s64[e*10 + kk] = (sn[2kk][e], sn[2kk+1][e])
// ============================================================
__global__ void __launch_bounds__(256, 3) k2(const float* __restrict__ features) {
    __shared__ ulonglong2 s_pk2[EE * 5];   // 20 KB
    __shared__ float s_sc[KK];
    int t = threadIdx.x;
    const int bpb = NN / 512;              // 256 blocks per batch
    int b  = blockIdx.x / bpb;
    int n0 = (blockIdx.x % bpb) * 512 + t;
    int n1 = n0 + 256;

    // pack sn into k-pair layout (scattered reads: g_sn is tiny, L2-hot)
    u64* s64 = (u64*)s_pk2;
    const float* snb = g_sn + (size_t)b * KK * EE;
    for (int i = t; i < EE * 10; i += 256) {
        int e = i / 10, kk = i - e * 10;
        s64[i] = pk(snb[(2 * kk) * EE + e], snb[(2 * kk + 1) * EE + e]);
    }
    if (t < KK) s_sc[t] = 0.f;
    __syncthreads();

    const float4* fv0 = (const float4*)(features + ((size_t)b * NN + n0) * EE);
    const float4* fv1 = (const float4*)(features + ((size_t)b * NN + n1) * EE);

    u64 acc0[10], acc1[10];
#pragma unroll
    for (int j = 0; j < 10; j++) { acc0[j] = 0; acc1[j] = 0; }
    u64 na0 = 0, na1 = 0;

#pragma unroll 2
    for (int e4 = 0; e4 < 64; e4++) {
        float4 f0 = __ldg(&fv0[e4]);
        float4 f1 = __ldg(&fv1[e4]);
        u64 p0a = pk(f0.x, f0.y), p0b = pk(f0.z, f0.w);
        u64 p1a = pk(f1.x, f1.y), p1b = pk(f1.z, f1.w);
        na0 = fma2(p0a, p0a, na0); na0 = fma2(p0b, p0b, na0);
        na1 = fma2(p1a, p1a, na1); na1 = fma2(p1b, p1b, na1);
        float fe0[4] = {f0.x, f0.y, f0.z, f0.w};
        float fe1[4] = {f1.x, f1.y, f1.z, f1.w};
#pragma unroll
        for (int e = 0; e < 4; e++) {
            u64 sp0 = pk(fe0[e], fe0[e]);
            u64 sp1 = pk(fe1[e], fe1[e]);
            const ulonglong2* srow = &s_pk2[(e4 * 4 + e) * 5];
#pragma unroll
            for (int kk2 = 0; kk2 < 5; kk2++) {
                ulonglong2 sv = srow[kk2];        // warp-uniform -> broadcast
                acc0[2 * kk2]     = fma2(sp0, sv.x, acc0[2 * kk2]);
                acc0[2 * kk2 + 1] = fma2(sp0, sv.y, acc0[2 * kk2 + 1]);
                acc1[2 * kk2]     = fma2(sp1, sv.x, acc1[2 * kk2]);
                acc1[2 * kk2 + 1] = fma2(sp1, sv.y, acc1[2 * kk2 + 1]);
            }
        }
    }

    // epilogue: unpack, normalize, softmax, store, score-reduce
    float d0[KK], d1[KK];
#pragma unroll
    for (int j = 0; j < 10; j++) {
        unpk(acc0[j], d0[2 * j], d0[2 * j + 1]);
        unpk(acc1[j], d1[2 * j], d1[2 * j + 1]);
    }
    float r0 = rsqrtf(fmaxf(f2sum(na0), 1e-24f));
    float r1 = rsqrtf(fmaxf(f2sum(na1), 1e-24f));
    float m0 = -1e30f, m1 = -1e30f;
#pragma unroll
    for (int k = 0; k < KK; k++) {
        d0[k] *= r0; d1[k] *= r1;
        m0 = fmaxf(m0, d0[k]); m1 = fmaxf(m1, d1[k]);
    }
    float s0 = 0.f, s1 = 0.f;
#pragma unroll
    for (int k = 0; k < KK; k++) {
        d0[k] = __expf(d0[k] - m0); s0 += d0[k];
        d1[k] = __expf(d1[k] - m1); s1 += d1[k];
    }
    float is0 = 1.f / s0, is1 = 1.f / s1;

#pragma unroll
    for (int k = 0; k < KK; k++) {
        float p0 = d0[k] * is0;
        float p1 = d1[k] * is1;
        size_t base = ((size_t)(b * KK + k)) * NN;
        g_mask[base + n0] = p0;
        g_mask[base + n1] = p1;
        float ws = p0 + p1;
        for (int off = 16; off; off >>= 1) ws += __shfl_xor_sync(0xffffffffu, ws, off);
        if ((t & 31) == 0) atomicAdd(&s_sc[k], ws);
    }
    __syncthreads();
    if (t < KK) atomicAdd(&g_scores[b * KK + t], s_sc[t]);
}

// ============================================================
// k3: NMS logic. Softmax rows sum to 1 => at most one value > 0.5 per row
// => inter diagonal => IoU off-diag 0 => suppression never fires.
// kept = valid columns in stable descending-score order, compacted.
// ============================================================
__global__ void k3() {
    if (threadIdx.x != 0) return;
    for (int b = 0; b < BB; b++) {
        float sc[KK]; bool used[KK];
        for (int k = 0; k < KK; k++) {
            sc[k] = g_scores[b * KK + k] * (1.f / (float)NN);
            used[k] = false;
        }
        int pos = 0;
        for (int r = 0; r < KK; r++) {
            int best = 0; float bs = -1e30f;
            for (int k = 0; k < KK; k++)
                if (!used[k] && sc[k] > bs) { bs = sc[k]; best = k; }
            used[best] = true;
            if (bs >= SCORE_THRESH) g_outsrc[b * KK + pos++] = best;
        }
        for (; pos < KK; pos++) g_outsrc[b * KK + pos] = -1;
    }
}

// ============================================================
// k4: out[b][p][n] = mask[b][src[p]][n] / (kept-sum + 1e-8). float4 per thread.
// ============================================================
__global__ void __launch_bounds__(256) k4(float* __restrict__ out) {
    __shared__ int src[KK];
    int t = threadIdx.x;
    const int bpb = NN / 1024;            // 128 blocks per batch, 4 n per thread
    int b  = blockIdx.x / bpb;
    int n4 = (blockIdx.x % bpb) * 256 + t;   // float4 index
    if (t < KK) src[t] = g_outsrc[b * KK + t];
    __syncthreads();

    const float4* mk = (const float4*)g_mask;
    float4 v[KK];
    float4 s = make_float4(0.f, 0.f, 0.f, 0.f);
#pragma unroll
    for (int p = 0; p < KK; p++) {
        int sk = src[p];
        if (sk >= 0) {
            v[p] = __ldg(&mk[((size_t)(b * KK + sk) * NN) / 4 + n4]);
        } else {
            v[p] = make_float4(0.f, 0.f, 0.f, 0.f);
        }
        s.x += v[p].x; s.y += v[p].y; s.z += v[p].z; s.w += v[p].w;
    }
    float4 is = make_float4(1.f / (s.x + 1e-8f), 1.f / (s.y + 1e-8f),
                            1.f / (s.z + 1e-8f), 1.f / (s.w + 1e-8f));
    float4* ov = (float4*)out;
#pragma unroll
    for (int p = 0; p < KK; p++) {
        float4 w = v[p];
        w.x *= is.x; w.y *= is.y; w.z *= is.z; w.w *= is.w;
        ov[((size_t)(b * KK + p) * NN) / 4 + n4] = w;
    }
}

// ============================================================
extern "C" void kernel_launch(void* const* d_in, const int* in_sizes, int n_in,
                              void* d_out, int out_size) {
    const float* features = (const float*)d_in[0];
    const float* slots    = (const float*)d_in[1];
    const float* w1       = (const float*)d_in[2];
    const float* b1       = (const float*)d_in[3];
    const float* gn_g     = (const float*)d_in[4];
    const float* gn_b     = (const float*)d_in[5];
    const float* w2       = (const float*)d_in[6];
    const float* b2       = (const float*)d_in[7];

    k1a<<<(BB * KK * EE) / 256, 256>>>(slots, w1, b1);
    k1b<<<BB * 4, 256>>>(gn_g, gn_b);
    k1c<<<BB * KK, 256>>>(w2, b2);
    k2<<<(BB * NN) / 512, 256>>>(features);
    k3<<<1, 32>>>();
    k4<<<(BB * NN) / 1024, 256>>>((float*)d_out);
}

// round 4
// speedup vs baseline: 1.5804x; 1.4016x over previous
#include <cuda_runtime.h>

#define BB 2
#define NN 131072
#define KK 20
#define EE 256
#define TEMP_INV 20.0f
#define SCORE_THRESH 0.04f

typedef unsigned long long u64;

// ---- packed f32x2 helpers (FFMA2 is PTX-only on sm_103a) ----
__device__ __forceinline__ u64 fma2(u64 a, u64 b, u64 c) {
    u64 d; asm("fma.rn.f32x2 %0, %1, %2, %3;" : "=l"(d) : "l"(a), "l"(b), "l"(c));
    return d;
}
__device__ __forceinline__ u64 pk(float a, float b) {
    u64 r; asm("mov.b64 %0, {%1, %2};" : "=l"(r) : "f"(a), "f"(b)); return r;
}
__device__ __forceinline__ float f2sum(u64 v) {
    float lo, hi; asm("mov.b64 {%0, %1}, %2;" : "=f"(lo), "=f"(hi) : "l"(v));
    return lo + hi;
}
__device__ __forceinline__ void unpk(u64 v, float& lo, float& hi) {
    asm("mov.b64 {%0, %1}, %2;" : "=f"(lo), "=f"(hi) : "l"(v));
}

// ---- scratch ----
__device__ float g_x[BB * KK * EE];
__device__ float g_sn[BB * KK * EE];            // normalized slots * (1/TEMP), [b][k][e]
__device__ u64   g_snpack[BB * EE * 10];        // [b][e][j]: (sn[2j][e], sn[2j+1][e])
__device__ float g_scores[BB * KK];
__device__ int   g_outsrc[BB * KK];
__device__ float g_mask[(size_t)BB * KK * NN];  // [b][k][n]

// sn in the constant bank -> LDCU (uniform port), zero l1tex traffic.
// c_sn2[b][e][m].x = pair k=(4m,4m+1), .y = pair k=(4m+2,4m+3)
__constant__ ulonglong2 c_sn2[BB][EE][5];       // 40 KB

// ============================================================
// k1a: x[b][k][o] = sum_e slots[b][k][e] * w1[o][e] + b1[o]
// ============================================================
__global__ void k1a(const float* __restrict__ slots, const float* __restrict__ w1,
                    const float* __restrict__ b1) {
    int g = blockIdx.x * 256 + threadIdx.x;
    if (g < BB * KK) g_scores[g] = 0.f;
    int b = g / (KK * EE);
    int rem = g % (KK * EE);
    int k = rem / EE;
    int o = rem % EE;
    const float4* sr = (const float4*)(slots + (size_t)(b * KK + k) * EE);
    const float4* wr = (const float4*)(w1 + (size_t)o * EE);
    u64 acc = 0;
#pragma unroll 8
    for (int i = 0; i < EE / 4; i++) {
        float4 s = __ldg(&sr[i]);
        float4 w = __ldg(&wr[i]);
        acc = fma2(pk(w.x, w.y), pk(s.x, s.y), acc);
        acc = fma2(pk(w.z, w.w), pk(s.z, s.w), acc);
    }
    g_x[(b * KK + k) * EE + o] = f2sum(acc) + __ldg(&b1[o]);
}

// ============================================================
// k1b: GroupNorm (64 ch x 20 slots) per (b, group) + affine + ReLU
// ============================================================
__global__ void k1b(const float* __restrict__ gn_g, const float* __restrict__ gn_b) {
    int b = blockIdx.x >> 2, grp = blockIdx.x & 3;
    int t = threadIdx.x;
    float s = 0.f, ss = 0.f;
    for (int i = t; i < KK * 64; i += 256) {
        int k = i >> 6, oo = (i & 63) + grp * 64;
        float v = g_x[(b * KK + k) * EE + oo];
        s += v; ss += v * v;
    }
    __shared__ float rs[8], rss[8];
    for (int off = 16; off; off >>= 1) {
        s  += __shfl_xor_sync(0xffffffffu, s, off);
        ss += __shfl_xor_sync(0xffffffffu, ss, off);
    }
    if ((t & 31) == 0) { rs[t >> 5] = s; rss[t >> 5] = ss; }
    __syncthreads();
    if (t == 0) {
        float a = 0.f, q = 0.f;
        for (int i = 0; i < 8; i++) { a += rs[i]; q += rss[i]; }
        rs[0] = a; rss[0] = q;
    }
    __syncthreads();
    float mu  = rs[0] * (1.f / 1280.f);
    float var = rss[0] * (1.f / 1280.f) - mu * mu;
    float sc  = rsqrtf(var + 1e-5f);
    for (int i = t; i < KK * 64; i += 256) {
        int k = i >> 6, oo = (i & 63) + grp * 64;
        int idx = (b * KK + k) * EE + oo;
        float v = (g_x[idx] - mu) * sc * __ldg(&gn_g[oo]) + __ldg(&gn_b[oo]);
        g_x[idx] = fmaxf(v, 0.f);
    }
}

// ============================================================
// k1c: slot + l2norm over f, scaled by 1/TEMP. Block per (b,k), thread=f.
// ============================================================
__global__ void k1c(const float* __restrict__ w2, const float* __restrict__ b2) {
    int b = blockIdx.x / KK, k = blockIdx.x % KK;
    int f = threadIdx.x;
    __shared__ float sx[EE];
    sx[f] = g_x[(b * KK + k) * EE + f];
    __syncthreads();
    const float4* wr = (const float4*)(w2 + (size_t)f * EE);
    const float4* xr = (const float4*)sx;
    u64 acc = 0;
#pragma unroll 8
    for (int i = 0; i < EE / 4; i++) {
        float4 w = __ldg(&wr[i]);
        float4 x = xr[i];
        acc = fma2(pk(w.x, w.y), pk(x.x, x.y), acc);
        acc = fma2(pk(w.z, w.w), pk(x.z, x.w), acc);
    }
    float d = f2sum(acc) + __ldg(&b2[f]);
    float q = d * d;
    __shared__ float rq[8];
    for (int off = 16; off; off >>= 1) q += __shfl_xor_sync(0xffffffffu, q, off);
    if ((f & 31) == 0) rq[f >> 5] = q;
    __syncthreads();
    __shared__ float rinv_s;
    if (f == 0) {
        float a = 0.f;
        for (int i = 0; i < 8; i++) a += rq[i];
        rinv_s = rsqrtf(fmaxf(a, 1e-24f)) * TEMP_INV;
    }
    __syncthreads();
    g_sn[(b * KK + k) * EE + f] = d * rinv_s;
}

// ============================================================
// k1d: repack sn into k-pair u64s for the constant bank.
// element (b,e,j): pk(sn[b][2j][e], sn[b][2j+1][e])
// ============================================================
__global__ void k1d() {
    int g = blockIdx.x * 256 + threadIdx.x;       // 0 .. BB*EE*10-1
    if (g >= BB * EE * 10) return;
    int b = g / (EE * 10);
    int rem = g % (EE * 10);
    int e = rem / 10, j = rem % 10;
    const float* snb = g_sn + (size_t)b * KK * EE;
    g_snpack[g] = pk(snb[(2 * j) * EE + e], snb[(2 * j + 1) * EE + e]);
}

// ============================================================
// k2: big GEMV-batch + softmax. R=2 rows/thread.
// sn comes from __constant__ (LDCU, uniform port) - l1tex only sees features.
// Templated on batch so constant offsets are compile-time uniform.
// ============================================================
template <int B_>
__global__ void __launch_bounds__(256, 3) k2(const float* __restrict__ features) {
    __shared__ float s_sc[KK];
    int t = threadIdx.x;
    int n0 = blockIdx.x * 512 + t;
    int n1 = n0 + 256;
    if (t < KK) s_sc[t] = 0.f;

    const float4* fv0 = (const float4*)(features + ((size_t)B_ * NN + n0) * EE);
    const float4* fv1 = (const float4*)(features + ((size_t)B_ * NN + n1) * EE);

    u64 acc0[10], acc1[10];
#pragma unroll
    for (int j = 0; j < 10; j++) { acc0[j] = 0; acc1[j] = 0; }
    u64 na0 = 0, na1 = 0;

#pragma unroll 4
    for (int e4 = 0; e4 < 64; e4++) {
        float4 f0 = __ldg(&fv0[e4]);
        float4 f1 = __ldg(&fv1[e4]);
        u64 p0a = pk(f0.x, f0.y), p0b = pk(f0.z, f0.w);
        u64 p1a = pk(f1.x, f1.y), p1b = pk(f1.z, f1.w);
        na0 = fma2(p0a, p0a, na0); na0 = fma2(p0b, p0b, na0);
        na1 = fma2(p1a, p1a, na1); na1 = fma2(p1b, p1b, na1);
        float fe0[4] = {f0.x, f0.y, f0.z, f0.w};
        float fe1[4] = {f1.x, f1.y, f1.z, f1.w};
#pragma unroll
        for (int e = 0; e < 4; e++) {
            u64 sp0 = pk(fe0[e], fe0[e]);
            u64 sp1 = pk(fe1[e], fe1[e]);
#pragma unroll
            for (int m = 0; m < 5; m++) {
                ulonglong2 sv = c_sn2[B_][e4 * 4 + e][m];   // LDCU path
                acc0[2 * m]     = fma2(sp0, sv.x, acc0[2 * m]);
                acc0[2 * m + 1] = fma2(sp0, sv.y, acc0[2 * m + 1]);
                acc1[2 * m]     = fma2(sp1, sv.x, acc1[2 * m]);
                acc1[2 * m + 1] = fma2(sp1, sv.y, acc1[2 * m + 1]);
            }
        }
    }

    float d0[KK], d1[KK];
#pragma unroll
    for (int j = 0; j < 10; j++) {
        unpk(acc0[j], d0[2 * j], d0[2 * j + 1]);
        unpk(acc1[j], d1[2 * j], d1[2 * j + 1]);
    }
    float r0 = rsqrtf(fmaxf(f2sum(na0), 1e-24f));
    float r1 = rsqrtf(fmaxf(f2sum(na1), 1e-24f));
    float m0 = -1e30f, m1 = -1e30f;
#pragma unroll
    for (int k = 0; k < KK; k++) {
        d0[k] *= r0; d1[k] *= r1;
        m0 = fmaxf(m0, d0[k]); m1 = fmaxf(m1, d1[k]);
    }
    float s0 = 0.f, s1 = 0.f;
#pragma unroll
    for (int k = 0; k < KK; k++) {
        d0[k] = __expf(d0[k] - m0); s0 += d0[k];
        d1[k] = __expf(d1[k] - m1); s1 += d1[k];
    }
    float is0 = 1.f / s0, is1 = 1.f / s1;
    __syncthreads();   // s_sc zero visible

#pragma unroll
    for (int k = 0; k < KK; k++) {
        float p0 = d0[k] * is0;
        float p1 = d1[k] * is1;
        size_t base = ((size_t)(B_ * KK + k)) * NN;
        g_mask[base + n0] = p0;
        g_mask[base + n1] = p1;
        float ws = p0 + p1;
        for (int off = 16; off; off >>= 1) ws += __shfl_xor_sync(0xffffffffu, ws, off);
        if ((t & 31) == 0) atomicAdd(&s_sc[k], ws);
    }
    __syncthreads();
    if (t < KK) atomicAdd(&g_scores[B_ * KK + t], s_sc[t]);
}

// ============================================================
// k3: NMS logic. Softmax rows sum to 1 => at most one value > 0.5 per row
// => inter diagonal => IoU off-diag 0 => suppression never fires.
// kept = valid columns in stable descending-score order, compacted.
// ============================================================
__global__ void k3() {
    if (threadIdx.x != 0) return;
    for (int b = 0; b < BB; b++) {
        float sc[KK]; bool used[KK];
        for (int k = 0; k < KK; k++) {
            sc[k] = g_scores[b * KK + k] * (1.f / (float)NN);
            used[k] = false;
        }
        int pos = 0;
        for (int r = 0; r < KK; r++) {
            int best = 0; float bs = -1e30f;
            for (int k = 0; k < KK; k++)
                if (!used[k] && sc[k] > bs) { bs = sc[k]; best = k; }
            used[best] = true;
            if (bs >= SCORE_THRESH) g_outsrc[b * KK + pos++] = best;
        }
        for (; pos < KK; pos++) g_outsrc[b * KK + pos] = -1;
    }
}

// ============================================================
// k4: out[b][p][n] = mask[b][src[p]][n] / (kept-sum + 1e-8). float4 per thread.
// ============================================================
__global__ void __launch_bounds__(256) k4(float* __restrict__ out) {
    __shared__ int src[KK];
    int t = threadIdx.x;
    const int bpb = NN / 1024;
    int b  = blockIdx.x / bpb;
    int n4 = (blockIdx.x % bpb) * 256 + t;
    if (t < KK) src[t] = g_outsrc[b * KK + t];
    __syncthreads();

    const float4* mk = (const float4*)g_mask;
    float4 v[KK];
    float4 s = make_float4(0.f, 0.f, 0.f, 0.f);
#pragma unroll
    for (int p = 0; p < KK; p++) {
        int sk = src[p];
        if (sk >= 0) {
            v[p] = __ldg(&mk[((size_t)(b * KK + sk) * NN) / 4 + n4]);
        } else {
            v[p] = make_float4(0.f, 0.f, 0.f, 0.f);
        }
        s.x += v[p].x; s.y += v[p].y; s.z += v[p].z; s.w += v[p].w;
    }
    float4 is = make_float4(1.f / (s.x + 1e-8f), 1.f / (s.y + 1e-8f),
                            1.f / (s.z + 1e-8f), 1.f / (s.w + 1e-8f));
    float4* ov = (float4*)out;
#pragma unroll
    for (int p = 0; p < KK; p++) {
        float4 w = v[p];
        w.x *= is.x; w.y *= is.y; w.z *= is.z; w.w *= is.w;
        ov[((size_t)(b * KK + p) * NN) / 4 + n4] = w;
    }
}

// ============================================================
extern "C" void kernel_launch(void* const* d_in, const int* in_sizes, int n_in,
                              void* d_out, int out_size) {
    const float* features = (const float*)d_in[0];
    const float* slots    = (const float*)d_in[1];
    const float* w1       = (const float*)d_in[2];
    const float* b1       = (const float*)d_in[3];
    const float* gn_g     = (const float*)d_in[4];
    const float* gn_b     = (const float*)d_in[5];
    const float* w2       = (const float*)d_in[6];
    const float* b2       = (const float*)d_in[7];

    k1a<<<(BB * KK * EE) / 256, 256>>>(slots, w1, b1);
    k1b<<<BB * 4, 256>>>(gn_g, gn_b);
    k1c<<<BB * KK, 256>>>(w2, b2);
    k1d<<<(BB * EE * 10 + 255) / 256, 256>>>();

    // stage packed sn into the constant bank (async D2D, graph-capturable)
    void* src = nullptr;
    cudaGetSymbolAddress(&src, g_snpack);
    cudaMemcpyToSymbolAsync(c_sn2, src, sizeof(u64) * BB * EE * 10, 0,
                            cudaMemcpyDeviceToDevice, 0);

    k2<0><<<NN / 512, 256>>>(features);
    k2<1><<<NN / 512, 256>>>(features);
    k3<<<1, 32>>>();
    k4<<<(BB * NN) / 1024, 256>>>((float*)d_out);
}